// round 16
// baseline (speedup 1.0000x reference)
#include <cuda_runtime.h>
#include <math_constants.h>
#include <cstdint>

#define BB 8
#define NN 4096
#define DD 16
#define OO 64
#define KK 20
#define KP 24            // per-split fast-pass pad
#define SPLIT 4          // candidate splits per query
#define QTR (NN/SPLIT)   // 1024 candidates per split
#define CNT (8LL*4096*20)

#define TQ 64            // threads per knn block (2 queries per thread)
#define QPB 128          // queries per knn block
#define TC 128           // candidate tile rows
#define BUFCAP 240       // per-query pending buffer (local mem, 8KiB guard)

// ---------------- scratch (static device globals: no allocation) ------------
__device__ float  g_u[BB*NN*OO];
__device__ float  g_v[BB*NN*OO];
__device__ int    g_idx[BB*NN*KK];          // final knn indices
__device__ int    g_pidx[BB*NN*SPLIT*KP];   // per-split fast top-24 indices
__device__ float  g_sqf[BB*NN];             // XLA-emulated fp32 sum(x*x)
__device__ double g_sum[OO];
__device__ double g_sumsq[OO];
__device__ float  g_a[OO];
__device__ float  g_c[OO];

// ---------------- kernel 0: zero accumulators --------------------------------
__global__ void zero_sums() {
    int t = threadIdx.x;
    if (t < OO) { g_sum[t] = 0.0; g_sumsq[t] = 0.0; }
}

// ---------------- kernel 0b: XLA-emulated per-point squared norms -----------
// DO NOT CHANGE (bit-exact emulation of reference rounding; validated R3).
__global__ void sq_kernel(const float* __restrict__ x) {
    int p = blockIdx.x * blockDim.x + threadIdx.x;
    const float4* xp = (const float4*)(x + (size_t)p * DD);
    float s[4];
#pragma unroll
    for (int i = 0; i < 4; i++) {
        float4 v = xp[i];
        float a = __fmul_rn(v.x, v.x);
        a = __fadd_rn(a, __fmul_rn(v.y, v.y));
        a = __fadd_rn(a, __fmul_rn(v.z, v.z));
        a = __fadd_rn(a, __fmul_rn(v.w, v.w));
        s[i] = a;
    }
    g_sqf[p] = __fadd_rn(__fadd_rn(s[0], s[2]), __fadd_rn(s[1], s[3]));
}

// ---------------- kernel 1: per-point projections u, v ----------------------
__global__ void proj_kernel(const float* __restrict__ x,
                            const float* __restrict__ W) {
    __shared__ float Wt[2*DD][OO];
    __shared__ float xr[4][DD];
    int tid = threadIdx.x;
    for (int i = tid; i < OO*2*DD; i += blockDim.x) {
        int o = i / (2*DD), c = i % (2*DD);
        Wt[c][o] = W[i];
    }
    int p0 = blockIdx.x * 4;
    if (tid < 4*DD) xr[tid >> 4][tid & 15] = x[p0*DD + tid];
    __syncthreads();
    int o  = tid & 63;
    int nl = tid >> 6;
    float cacc = 0.f, facc = 0.f;
#pragma unroll
    for (int d = 0; d < DD; d++) {
        float xv = xr[nl][d];
        cacc = fmaf(Wt[d][o],      xv, cacc);
        facc = fmaf(Wt[DD + d][o], xv, facc);
    }
    int p = p0 + nl;
    g_u[p*OO + o] = cacc - facc;
    g_v[p*OO + o] = facc;
}

// ---------------- kNN helpers ------------------------------------------------
__device__ __forceinline__ float dot4(float4 a, float4 b) {
    return fmaf(a.x, b.x, fmaf(a.y, b.y, fmaf(a.z, b.z, a.w * b.w)));
}

__device__ __forceinline__ unsigned long long pack_key(float d, int gidx) {
    unsigned s = __float_as_uint(d);
    s ^= ((unsigned)((int)s >> 31)) | 0x80000000u;   // monotone f32->u32
    return ((unsigned long long)s << 32) | (unsigned)gidx;
}

__device__ __forceinline__ float unpack_d(unsigned long long key) {
    unsigned s = (unsigned)(key >> 32);
    s = (s & 0x80000000u) ? (s ^ 0x80000000u) : ~s;
    return __uint_as_float(s);
}

// drain pending local buffer into thread-local sorted top-KP (rare path).
// u64 key compare keeps exact (d asc, idx asc) == jax top_k tie-breaking.
__device__ __forceinline__ void compactl(unsigned long long* __restrict__ buf,
                                         int& cnt,
                                         unsigned long long* __restrict__ hp,
                                         float& thr) {
    unsigned long long worst = hp[KP-1];
    for (int i = 0; i < cnt; i++) {
        unsigned long long key = buf[i];
        if (key < worst) {
            int j = KP - 1;
            while (j > 0 && key < hp[j-1]) { hp[j] = hp[j-1]; j--; }
            hp[j] = key;
            worst = hp[KP-1];
        }
    }
    cnt = 0;
    thr = unpack_d(worst);
}

// ---------------- kernel 2a: fast-pass kNN (2 queries/thread, cap 168) ------
// Proven R14 code shape: ONE body instantiation, ONE in-loop compact site.
// 5 LDS wavefronts per staged candidate feed 2 query-visits.
// grid = BB * (NN/QPB) * SPLIT = 1024 blocks of 64 threads.
__global__ __launch_bounds__(TQ, 6) void knn_part_kernel(const float* __restrict__ x) {
    __shared__ float4 xs[TC*4];                  // 8KB
    __shared__ float  sqs[TC];                   // 0.5KB

    int tid   = threadIdx.x;
    int b     = blockIdx.x >> 7;
    int rem   = blockIdx.x & 127;
    int qg    = rem >> 2;
    int split = rem & (SPLIT-1);
    int qn0   = qg * QPB + tid;
    int qn1   = qn0 + TQ;
    int cbase = split * QTR;

    const float* xb  = x + (size_t)b * NN * DD;
    const float* sqb = g_sqf + (size_t)b * NN;

    const float4* qpa = (const float4*)(xb + (size_t)qn0 * DD);
    const float4* qpb = (const float4*)(xb + (size_t)qn1 * DD);
    float4 a0 = qpa[0], a1 = qpa[1], a2 = qpa[2], a3 = qpa[3];
    float4 b0 = qpb[0], b1 = qpb[1], b2 = qpb[2], b3 = qpb[3];
    float sqnA = sqb[qn0], sqnB = sqb[qn1];

    unsigned long long hp0[KP], hp1[KP];         // local mem (rare access)
#pragma unroll
    for (int j = 0; j < KP; j++) { hp0[j] = ~0ull; hp1[j] = ~0ull; }
    unsigned long long buf0[BUFCAP], buf1[BUFCAP];
    int cnt0 = 0, cnt1 = 0;
    float thr0 = CUDART_INF_F, thr1 = CUDART_INF_F;

    for (int t0 = 0; t0 < QTR; t0 += TC) {
        // cooperative stage: 2 rows per thread
#pragma unroll
        for (int i = 0; i < TC/TQ; i++) {
            int r = tid + i * TQ;
            const float4* src = (const float4*)(xb + (size_t)(cbase + t0 + r) * DD);
            xs[r*4 + 0] = src[0]; xs[r*4 + 1] = src[1];
            xs[r*4 + 2] = src[2]; xs[r*4 + 3] = src[3];
            sqs[r] = sqb[cbase + t0 + r];
        }
        __syncthreads();

#pragma unroll 2
        for (int m = 0; m < TC; m++) {
            float4 c0 = xs[m*4+0], c1 = xs[m*4+1], c2 = xs[m*4+2], c3 = xs[m*4+3];
            float s = sqs[m];
            float dA = (dot4(a0,c0) + dot4(a1,c1)) + (dot4(a2,c2) + dot4(a3,c3));
            float dB = (dot4(b0,c0) + dot4(b1,c1)) + (dot4(b2,c2) + dot4(b3,c3));
            float d2A = fmaf(-2.f, dA, sqnA + s);
            float d2B = fmaf(-2.f, dB, sqnB + s);
            int gi = cbase + t0 + m;
            if (d2A < thr0) buf0[cnt0++] = pack_key(d2A, gi);
            if (d2B < thr1) buf1[cnt1++] = pack_key(d2B, gi);
        }
        __syncthreads();

        // establish thresholds after first tile; afterwards only drain when a
        // buffer could overflow within the next tile (warp-uniform trigger).
        bool need = (t0 == 0) ||
                    __any_sync(0xffffffffu,
                               (cnt0 >= BUFCAP - TC) | (cnt1 >= BUFCAP - TC));
        if (need) {
            compactl(buf0, cnt0, hp0, thr0);
            compactl(buf1, cnt1, hp1, thr1);
        }
    }
    compactl(buf0, cnt0, hp0, thr0);
    compactl(buf1, cnt1, hp1, thr1);

    int* o0 = g_pidx + (((size_t)b * NN + qn0) * SPLIT + split) * KP;
    int* o1 = g_pidx + (((size_t)b * NN + qn1) * SPLIT + split) * KP;
#pragma unroll
    for (int j = 0; j < KP; j++) {
        o0[j] = (int)(hp0[j] & 0xFFFFFFFFu);
        o1[j] = (int)(hp1[j] & 0xFFFFFFFFu);
    }
}

// ---------------- kernel 2b: merge splits + emulated-reference refinement ---
// FROZEN numerics (validated R3): serial-FFMA dot k ascending;
// d2 = fl( fl(sqn + sqc) - fl(2*dot) ); u64 key = (monotone d2, idx).
#define TQM 64
__global__ __launch_bounds__(TQM) void knn_merge_kernel(const float* __restrict__ x) {
    int tid = threadIdx.x;
    int b   = blockIdx.x >> 6;
    int qn  = ((blockIdx.x & 63) << 6) + tid;
    const float* xb  = x + (size_t)b * NN * DD;
    const float* sqb = g_sqf + (size_t)b * NN;

    const float4* qp = (const float4*)(xb + (size_t)qn * DD);
    float4 q0 = qp[0], q1 = qp[1], q2 = qp[2], q3 = qp[3];
    float sqn = sqb[qn];

    unsigned long long outk[KK];
#pragma unroll
    for (int j = 0; j < KK; j++) outk[j] = 0xFFFFFFFFFFFFFFFFull;

    const int* pin = g_pidx + ((size_t)b * NN + qn) * SPLIT * KP;
#pragma unroll 4
    for (int j = 0; j < SPLIT * KP; j++) {
        int ci = pin[j];
        const float4* cp = (const float4*)(xb + (size_t)ci * DD);
        float4 c0 = cp[0], c1 = cp[1], c2 = cp[2], c3 = cp[3];
        float acc = 0.f;
        acc = fmaf(q0.x, c0.x, acc); acc = fmaf(q0.y, c0.y, acc);
        acc = fmaf(q0.z, c0.z, acc); acc = fmaf(q0.w, c0.w, acc);
        acc = fmaf(q1.x, c1.x, acc); acc = fmaf(q1.y, c1.y, acc);
        acc = fmaf(q1.z, c1.z, acc); acc = fmaf(q1.w, c1.w, acc);
        acc = fmaf(q2.x, c2.x, acc); acc = fmaf(q2.y, c2.y, acc);
        acc = fmaf(q2.z, c2.z, acc); acc = fmaf(q2.w, c2.w, acc);
        acc = fmaf(q3.x, c3.x, acc); acc = fmaf(q3.y, c3.y, acc);
        acc = fmaf(q3.z, c3.z, acc); acc = fmaf(q3.w, c3.w, acc);
        float ssum = __fadd_rn(sqn, sqb[ci]);
        float d2   = __fsub_rn(ssum, __fmul_rn(2.0f, acc));
        unsigned long long key = pack_key(d2, ci);
        if (key < outk[KK-1]) {
            outk[KK-1] = key;
#pragma unroll
            for (int t = KK-1; t > 0; --t) {
                if (outk[t] < outk[t-1]) {
                    unsigned long long tmp = outk[t];
                    outk[t] = outk[t-1]; outk[t-1] = tmp;
                } else break;
            }
        }
    }

    int* outp = g_idx + ((size_t)b * NN + qn) * KK;
#pragma unroll
    for (int j = 0; j < KK; j++) outp[j] = (int)(outk[j] & 0xFFFFFFFFu);
}

// ---------------- kernel 3: per-channel sum / sumsq over (b,n,k) ------------
__global__ void sums_kernel() {
    int tid = threadIdx.x;
    int o = tid & 63;
    int g = tid >> 6;
    float s = 0.f, s2 = 0.f;
    int r0 = (blockIdx.x * 4 + g) * 32;
    for (int i = 0; i < 32; i++) {
        int r = r0 + i;
        int b = r >> 12;
        float u = g_u[(size_t)r * OO + o];
        const int* ip = g_idx + (size_t)r * KK;
#pragma unroll
        for (int k = 0; k < KK; k++) {
            int gi = ip[k];
            float h = u + g_v[(((size_t)b << 12) + gi) * OO + o];
            s += h;
            s2 = fmaf(h, h, s2);
        }
    }
    atomicAdd(&g_sum[o],   (double)s);
    atomicAdd(&g_sumsq[o], (double)s2);
}

// ---------------- kernel 4: finalize affine coefficients --------------------
__global__ void finalize_kernel(const float* __restrict__ gamma,
                                const float* __restrict__ beta) {
    int o = threadIdx.x;
    if (o < OO) {
        double mean = g_sum[o] / (double)CNT;
        double var  = g_sumsq[o] / (double)CNT - mean * mean;
        double rstd = 1.0 / sqrt(var + 1e-5);
        float a = gamma[o] * (float)rstd;
        g_a[o] = a;
        g_c[o] = fmaf(-(float)mean, a, beta[o]);
    }
}

// ---------------- kernel 5: write output (coalesced, smem-staged) -----------
__global__ void out_kernel(float* __restrict__ out) {
    __shared__ float su[NN];
    __shared__ float sv[NN];
    int b = blockIdx.x >> 6;
    int o = blockIdx.x & 63;
    float a = g_a[o], c = g_c[o];
    int tid = threadIdx.x;
    size_t base = (size_t)b * NN * OO;
    for (int i = tid; i < NN; i += blockDim.x) {
        su[i] = fmaf(a, g_u[base + (size_t)i * OO + o], c);
        sv[i] = a * g_v[base + (size_t)i * OO + o];
    }
    __syncthreads();
    const int* ip = g_idx + (size_t)b * NN * KK;
    float* op = out + (size_t)blockIdx.x * (NN * KK);
    for (int e = tid; e < NN * KK; e += blockDim.x) {
        int n = e / KK;
        int gi = ip[e];
        float y = su[n] + sv[gi];
        op[e] = fmaxf(y, 0.f);
    }
}

// ---------------- launcher ---------------------------------------------------
extern "C" void kernel_launch(void* const* d_in, const int* in_sizes, int n_in,
                              void* d_out, int out_size) {
    const float* x     = (const float*)d_in[0];
    const float* W     = (const float*)d_in[1];
    const float* gamma = (const float*)d_in[2];
    const float* beta  = (const float*)d_in[3];
    float* out = (float*)d_out;

    zero_sums<<<1, 64>>>();
    sq_kernel<<<BB*NN/256, 256>>>(x);
    proj_kernel<<<BB*NN/4, 256>>>(x, W);
    knn_part_kernel<<<BB*(NN/QPB)*SPLIT, TQ>>>(x);
    knn_merge_kernel<<<BB*NN/TQM, TQM>>>(x);
    sums_kernel<<<BB*NN/128, 256>>>();
    finalize_kernel<<<1, 64>>>(gamma, beta);
    out_kernel<<<BB*OO, 256>>>(out);
}

// round 17
// speedup vs baseline: 1.6383x; 1.6383x over previous
#include <cuda_runtime.h>
#include <math_constants.h>
#include <cstdint>

#define BB 8
#define NN 4096
#define DD 16
#define OO 64
#define KK 20
#define KP 24            // per-half fast-pass pad
#define SPLIT 2          // candidate split per query
#define HALF (NN/SPLIT)
#define CNT (8LL*4096*20)

#define TQ 64            // queries per block (1 thread = 1 query)
#define TC 256           // candidate tile rows
#define BUFCAP 512       // per-query pending buffer (local mem)

// ---------------- scratch (static device globals: no allocation) ------------
__device__ float  g_u[BB*NN*OO];
__device__ float  g_v[BB*NN*OO];
__device__ int    g_idx[BB*NN*KK];          // final knn indices
__device__ int    g_pidx[BB*NN*SPLIT*KP];   // per-half fast top-24 indices
__device__ float  g_sqf[BB*NN];             // XLA-emulated fp32 sum(x*x)
__device__ double g_sum[OO];
__device__ double g_sumsq[OO];
__device__ float  g_a[OO];
__device__ float  g_c[OO];

// ---------------- kernel 0: zero accumulators --------------------------------
__global__ void zero_sums() {
    int t = threadIdx.x;
    if (t < OO) { g_sum[t] = 0.0; g_sumsq[t] = 0.0; }
}

// ---------------- kernel 0b: XLA-emulated per-point squared norms -----------
// DO NOT CHANGE (bit-exact emulation of reference rounding; validated R3).
__global__ void sq_kernel(const float* __restrict__ x) {
    int p = blockIdx.x * blockDim.x + threadIdx.x;
    const float4* xp = (const float4*)(x + (size_t)p * DD);
    float s[4];
#pragma unroll
    for (int i = 0; i < 4; i++) {
        float4 v = xp[i];
        float a = __fmul_rn(v.x, v.x);
        a = __fadd_rn(a, __fmul_rn(v.y, v.y));
        a = __fadd_rn(a, __fmul_rn(v.z, v.z));
        a = __fadd_rn(a, __fmul_rn(v.w, v.w));
        s[i] = a;
    }
    g_sqf[p] = __fadd_rn(__fadd_rn(s[0], s[2]), __fadd_rn(s[1], s[3]));
}

// ---------------- kernel 1: per-point projections u, v ----------------------
__global__ void proj_kernel(const float* __restrict__ x,
                            const float* __restrict__ W) {
    __shared__ float Wt[2*DD][OO];
    __shared__ float xr[4][DD];
    int tid = threadIdx.x;
    for (int i = tid; i < OO*2*DD; i += blockDim.x) {
        int o = i / (2*DD), c = i % (2*DD);
        Wt[c][o] = W[i];
    }
    int p0 = blockIdx.x * 4;
    if (tid < 4*DD) xr[tid >> 4][tid & 15] = x[p0*DD + tid];
    __syncthreads();
    int o  = tid & 63;
    int nl = tid >> 6;
    float cacc = 0.f, facc = 0.f;
#pragma unroll
    for (int d = 0; d < DD; d++) {
        float xv = xr[nl][d];
        cacc = fmaf(Wt[d][o],      xv, cacc);
        facc = fmaf(Wt[DD + d][o], xv, facc);
    }
    int p = p0 + nl;
    g_u[p*OO + o] = cacc - facc;
    g_v[p*OO + o] = facc;
}

// ---------------- kNN helpers (R4 verbatim) ----------------------------------
__device__ __forceinline__ float dot4(float4 a, float4 b) {
    return fmaf(a.x, b.x, fmaf(a.y, b.y, fmaf(a.z, b.z, a.w * b.w)));
}

__device__ __forceinline__ unsigned long long pack_key(float d, int gidx) {
    unsigned s = __float_as_uint(d);
    s ^= ((unsigned)((int)s >> 31)) | 0x80000000u;   // monotone f32->u32
    return ((unsigned long long)s << 32) | (unsigned)gidx;
}

__device__ __forceinline__ float unpack_d2(unsigned long long key) {
    unsigned s = (unsigned)(key >> 32);
    s = (s & 0x80000000u) ? (s ^ 0x80000000u) : ~s;
    return __uint_as_float(s);
}

// drain pending buffer into this thread's smem-resident sorted top-24 column.
// hcol[j*TQ] = j-th best key. Rare path (runs a few times per thread total).
__device__ __forceinline__ void compact(unsigned long long* __restrict__ buf,
                                        int& cnt,
                                        unsigned long long* __restrict__ hcol,
                                        float& thr) {
    unsigned long long worst = hcol[(KP-1)*TQ];
    for (int i = 0; i < cnt; i++) {
        unsigned long long key = buf[i];
        if (key < worst) {
            int j = KP - 1;
            while (j > 0) {
                unsigned long long cur = hcol[(j-1)*TQ];
                if (key < cur) { hcol[j*TQ] = cur; j--; }
                else break;
            }
            hcol[j*TQ] = key;
            worst = hcol[(KP-1)*TQ];
        }
    }
    cnt = 0;
    thr = unpack_d2(worst);
}

// ---------------- kernel 2a: fast-pass kNN (R4 verbatim, measured 946us) ----
// grid = BB * (NN/TQ) * SPLIT blocks; 1 thread = 1 query over HALF candidates.
__global__ __launch_bounds__(TQ) void knn_part_kernel(const float* __restrict__ x) {
    __shared__ float4 xs[TC*4];
    __shared__ float  sqs[TC];
    __shared__ unsigned long long heap[KP*TQ];   // [j][thread]

    int tid  = threadIdx.x;
    int bi   = blockIdx.x;
    int b    = bi >> 7;            // 128 blocks per batch
    int rem  = bi & 127;
    int qg   = rem >> 1;
    int half = rem & 1;
    int qn   = qg * TQ + tid;
    int cbase = half * HALF;

    const float* xb  = x + (size_t)b * NN * DD;
    const float* sqb = g_sqf + (size_t)b * NN;

    const float4* qp = (const float4*)(xb + (size_t)qn * DD);
    float4 q0 = qp[0], q1 = qp[1], q2 = qp[2], q3 = qp[3];
    float sqn = sqb[qn];

#pragma unroll
    for (int j = 0; j < KP; j++) heap[j*TQ + tid] = 0xFFFFFFFFFFFFFFFFull;
    unsigned long long* hcol = heap + tid;

    unsigned long long buf[BUFCAP];   // local memory (dynamically indexed)
    int cnt = 0;
    float thr = CUDART_INF_F;

    for (int t0 = 0; t0 < HALF; t0 += TC) {
        // stage tile
#pragma unroll
        for (int i = 0; i < TC/TQ; i++) {
            int r = tid + i * TQ;
            const float4* src = (const float4*)(xb + (size_t)(cbase + t0 + r) * DD);
            xs[r*4 + 0] = src[0]; xs[r*4 + 1] = src[1];
            xs[r*4 + 2] = src[2]; xs[r*4 + 3] = src[3];
            sqs[r] = sqb[cbase + t0 + r];
        }
        __syncthreads();

#pragma unroll 4
        for (int m = 0; m < TC; m++) {
            float4 c0 = xs[m*4+0], c1 = xs[m*4+1], c2 = xs[m*4+2], c3 = xs[m*4+3];
            float d  = (dot4(q0,c0) + dot4(q1,c1)) + (dot4(q2,c2) + dot4(q3,c3));
            float d2 = fmaf(-2.f, d, sqn + sqs[m]);
            if (d2 < thr) {
                buf[cnt++] = pack_key(d2, cbase + t0 + m);
            }
        }
        __syncthreads();

        // establish threshold after first tile; afterwards only drain when the
        // buffer could overflow within the next tile (warp-uniform trigger).
        bool need = (t0 == 0) || __any_sync(0xffffffffu, cnt >= BUFCAP - TC);
        if (need) compact(buf, cnt, hcol, thr);
    }
    compact(buf, cnt, hcol, thr);

    int* outp = g_pidx + (((size_t)b * NN + qn) * SPLIT + half) * KP;
#pragma unroll
    for (int j = 0; j < KP; j++) outp[j] = (int)(hcol[j*TQ] & 0xFFFFFFFFu);
}

// ---------------- kernel 2b: merge halves, 2 threads per query --------------
// FROZEN per-candidate numerics (validated R3): serial-FFMA dot k ascending;
// d2 = fl( fl(sqn + sqc) - fl(2*dot) ); u64 key = (monotone d2, idx).
// Thread parity h handles finalists [h*KP, h*KP+KP); each builds a sorted
// top-20; the pair's two sorted lists (disjoint candidate sets) are merged
// exactly by a 20-step two-pointer pass.
#define MQ 64    // queries per merge block (128 threads)
__global__ __launch_bounds__(2*MQ) void knn_merge_kernel(const float* __restrict__ x) {
    __shared__ unsigned long long sk[MQ][2][KK];   // 20KB

    int tid = threadIdx.x;
    int ql  = tid >> 1;
    int h   = tid & 1;
    int b   = blockIdx.x >> 6;
    int qn  = ((blockIdx.x & 63) << 6) + ql;

    const float* xb  = x + (size_t)b * NN * DD;
    const float* sqb = g_sqf + (size_t)b * NN;

    const float4* qp = (const float4*)(xb + (size_t)qn * DD);
    float4 q0 = qp[0], q1 = qp[1], q2 = qp[2], q3 = qp[3];
    float sqn = sqb[qn];

    unsigned long long outk[KK];
#pragma unroll
    for (int j = 0; j < KK; j++) outk[j] = 0xFFFFFFFFFFFFFFFFull;

    const int* pin = g_pidx + ((size_t)b * NN + qn) * SPLIT * KP + h * KP;
#pragma unroll 4
    for (int j = 0; j < KP; j++) {
        int ci = pin[j];
        const float4* cp = (const float4*)(xb + (size_t)ci * DD);
        float4 c0 = cp[0], c1 = cp[1], c2 = cp[2], c3 = cp[3];
        float acc = 0.f;
        acc = fmaf(q0.x, c0.x, acc); acc = fmaf(q0.y, c0.y, acc);
        acc = fmaf(q0.z, c0.z, acc); acc = fmaf(q0.w, c0.w, acc);
        acc = fmaf(q1.x, c1.x, acc); acc = fmaf(q1.y, c1.y, acc);
        acc = fmaf(q1.z, c1.z, acc); acc = fmaf(q1.w, c1.w, acc);
        acc = fmaf(q2.x, c2.x, acc); acc = fmaf(q2.y, c2.y, acc);
        acc = fmaf(q2.z, c2.z, acc); acc = fmaf(q2.w, c2.w, acc);
        acc = fmaf(q3.x, c3.x, acc); acc = fmaf(q3.y, c3.y, acc);
        acc = fmaf(q3.z, c3.z, acc); acc = fmaf(q3.w, c3.w, acc);
        float ssum = __fadd_rn(sqn, sqb[ci]);
        float d2   = __fsub_rn(ssum, __fmul_rn(2.0f, acc));
        unsigned long long key = pack_key(d2, ci);
        if (key < outk[KK-1]) {
            outk[KK-1] = key;
#pragma unroll
            for (int t = KK-1; t > 0; --t) {
                if (outk[t] < outk[t-1]) {
                    unsigned long long tmp = outk[t];
                    outk[t] = outk[t-1]; outk[t-1] = tmp;
                } else break;
            }
        }
    }

#pragma unroll
    for (int j = 0; j < KK; j++) sk[ql][h][j] = outk[j];
    __syncthreads();

    if (h == 0) {
        int* outp = g_idx + ((size_t)b * NN + qn) * KK;
        int ia = 0, ib = 0;
#pragma unroll
        for (int j = 0; j < KK; j++) {
            unsigned long long ka = sk[ql][0][ia];
            unsigned long long kb = sk[ql][1][ib];
            if (ka < kb) { outp[j] = (int)(ka & 0xFFFFFFFFu); ia++; }
            else         { outp[j] = (int)(kb & 0xFFFFFFFFu); ib++; }
        }
    }
}

// ---------------- kernel 3: per-channel sum / sumsq over (b,n,k) ------------
__global__ void sums_kernel() {
    int tid = threadIdx.x;
    int o = tid & 63;
    int g = tid >> 6;
    float s = 0.f, s2 = 0.f;
    int r0 = (blockIdx.x * 4 + g) * 32;
    for (int i = 0; i < 32; i++) {
        int r = r0 + i;
        int b = r >> 12;
        float u = g_u[(size_t)r * OO + o];
        const int* ip = g_idx + (size_t)r * KK;
#pragma unroll
        for (int k = 0; k < KK; k++) {
            int gi = ip[k];
            float h = u + g_v[(((size_t)b << 12) + gi) * OO + o];
            s += h;
            s2 = fmaf(h, h, s2);
        }
    }
    atomicAdd(&g_sum[o],   (double)s);
    atomicAdd(&g_sumsq[o], (double)s2);
}

// ---------------- kernel 4: finalize affine coefficients --------------------
__global__ void finalize_kernel(const float* __restrict__ gamma,
                                const float* __restrict__ beta) {
    int o = threadIdx.x;
    if (o < OO) {
        double mean = g_sum[o] / (double)CNT;
        double var  = g_sumsq[o] / (double)CNT - mean * mean;
        double rstd = 1.0 / sqrt(var + 1e-5);
        float a = gamma[o] * (float)rstd;
        g_a[o] = a;
        g_c[o] = fmaf(-(float)mean, a, beta[o]);
    }
}

// ---------------- kernel 5: write output (coalesced, smem-staged) -----------
__global__ void out_kernel(float* __restrict__ out) {
    __shared__ float su[NN];
    __shared__ float sv[NN];
    int b = blockIdx.x >> 6;
    int o = blockIdx.x & 63;
    float a = g_a[o], c = g_c[o];
    int tid = threadIdx.x;
    size_t base = (size_t)b * NN * OO;
    for (int i = tid; i < NN; i += blockDim.x) {
        su[i] = fmaf(a, g_u[base + (size_t)i * OO + o], c);
        sv[i] = a * g_v[base + (size_t)i * OO + o];
    }
    __syncthreads();
    const int* ip = g_idx + (size_t)b * NN * KK;
    float* op = out + (size_t)blockIdx.x * (NN * KK);
    for (int e = tid; e < NN * KK; e += blockDim.x) {
        int n = e / KK;
        int gi = ip[e];
        float y = su[n] + sv[gi];
        op[e] = fmaxf(y, 0.f);
    }
}

// ---------------- launcher ---------------------------------------------------
extern "C" void kernel_launch(void* const* d_in, const int* in_sizes, int n_in,
                              void* d_out, int out_size) {
    const float* x     = (const float*)d_in[0];
    const float* W     = (const float*)d_in[1];
    const float* gamma = (const float*)d_in[2];
    const float* beta  = (const float*)d_in[3];
    float* out = (float*)d_out;

    zero_sums<<<1, 64>>>();
    sq_kernel<<<BB*NN/256, 256>>>(x);
    proj_kernel<<<BB*NN/4, 256>>>(x, W);
    knn_part_kernel<<<BB*(NN/TQ)*SPLIT, TQ>>>(x);
    knn_merge_kernel<<<BB*NN/MQ, 2*MQ>>>(x);
    sums_kernel<<<BB*NN/128, 256>>>();
    finalize_kernel<<<1, 64>>>(gamma, beta);
    out_kernel<<<BB*OO, 256>>>(out);
}